// round 5
// baseline (speedup 1.0000x reference)
#include <cuda_runtime.h>
#include <math.h>
#include <float.h>

#define DDEPTH 7
#define IND   128
#define GRIDN 128
#define HIDN  256
#define BATCHN 2048
#define NT    129          // t in 0..128
#define TROW  512          // floats per table row: (P1,P2) float2 per h

// k_main tiling
#define MAIN_TPB 512
#define BCB   512          // batches per CTA
#define IPC   16           // i's per CTA
#define NIC   8            // i-chunk count (128/IPC)
#define ROWF4 32           // float4 per 64-h row slice
#define STAGE_N (NT * ROWF4)                 // 4128 float4 per buffer
#define SMEM_MAIN (2 * STAGE_N * 16 + IPC * BCB * 4)   // 164864 bytes

// ---------------- scratch (static device memory; no allocation) ----------------
__device__ float g_xmin[IND];
__device__ float g_xmax[IND];
__device__ float g_Zt[IND * BATCHN];             // z transposed: [i][b]
__device__ float g_sg[DDEPTH * IND * GRIDN];     // sorted grids
__device__ int   g_perm[DDEPTH * IND * GRIDN];   // permutation
__device__ float g_T[(size_t)DDEPTH * IND * NT * TROW];   // 236.7 MB prefix tables (c_d folded)
__device__ unsigned char g_tmap[(size_t)DDEPTH * IND * BATCHN];
__device__ float g_Hp[(size_t)NIC * BATCHN * HIDN];       // i-split partials (16.8 MB)
__device__ float g_Ha[BATCHN * HIDN];
__device__ float g_Hb[BATCHN * HIDN];
__device__ double g_sum[HIDN];
__device__ double g_sumsq[HIDN];
__device__ float2 g_bnp[HIDN];

// ---------------- cp.async helpers ----------------
__device__ __forceinline__ void cp16(void* dst_smem, const void* src) {
    unsigned int d = (unsigned int)__cvta_generic_to_shared(dst_smem);
    asm volatile("cp.async.cg.shared.global [%0], [%1], 16;\n" :: "r"(d), "l"(src));
}
#define CP_COMMIT() asm volatile("cp.async.commit_group;\n" ::: "memory")
#define CP_WAIT1()  asm volatile("cp.async.wait_group 1;\n" ::: "memory")
#define CP_WAIT0()  asm volatile("cp.async.wait_group 0;\n" ::: "memory")

// ---------------- 1. per-feature min/max over batch ----------------
__global__ void k_minmax(const float* __restrict__ x) {
    int i = blockIdx.x;
    float mn = FLT_MAX, mx = -FLT_MAX;
    for (int b = threadIdx.x; b < BATCHN; b += blockDim.x) {
        float v = x[b * IND + i];
        mn = fminf(mn, v);
        mx = fmaxf(mx, v);
    }
    __shared__ float smn[256], smx[256];
    smn[threadIdx.x] = mn; smx[threadIdx.x] = mx;
    __syncthreads();
    for (int s = 128; s > 0; s >>= 1) {
        if (threadIdx.x < s) {
            smn[threadIdx.x] = fminf(smn[threadIdx.x], smn[threadIdx.x + s]);
            smx[threadIdx.x] = fmaxf(smx[threadIdx.x], smx[threadIdx.x + s]);
        }
        __syncthreads();
    }
    if (threadIdx.x == 0) { g_xmin[i] = smn[0]; g_xmax[i] = smx[0]; }
}

// ---------------- 2. z transposed: g_Zt[i][b] ----------------
__global__ void k_z(const float* __restrict__ x) {
    int idx = blockIdx.x * blockDim.x + threadIdx.x;
    if (idx < BATCHN * IND) {
        int i = idx & (IND - 1);
        int b = idx >> 7;
        g_Zt[i * BATCHN + b] = (x[idx] - g_xmin[i]) / (g_xmax[i] - g_xmin[i] + 1e-6f);
    }
}

// ---------------- 3. sort grids per (d,i) via rank ----------------
__global__ void k_sort(const float* __restrict__ grids) {
    int di = blockIdx.x;
    int t  = threadIdx.x;
    __shared__ float sg[GRIDN];
    float g = grids[di * GRIDN + t];
    sg[t] = g;
    __syncthreads();
    int r = 0;
    #pragma unroll 8
    for (int j = 0; j < GRIDN; j++) {
        float gj = sg[j];
        r += (gj < g) || (gj == g && j < t);
    }
    g_sg[di * GRIDN + r]   = g;
    g_perm[di * GRIDN + r] = t;
}

// ---------------- 4. prefix tables with c_d folded in ----------------
__global__ void __launch_bounds__(256) k_table(const float* __restrict__ fs,
                                               const float* __restrict__ ds) {
    __shared__ float ssg[GRIDN];
    __shared__ int   spm[GRIDN];
    int di = blockIdx.x;
    int d  = di >> 7;
    int h  = threadIdx.x;
    if (h < GRIDN) {
        ssg[h] = g_sg[di * GRIDN + h];
        spm[h] = g_perm[di * GRIDN + h];
    }
    // depth suffix-softmax weight c_d (redundant per thread, tiny)
    float w[DDEPTH], m = -FLT_MAX;
    for (int k = 0; k < DDEPTH; k++) m = fmaxf(m, ds[k]);
    float ssum = 0.f;
    for (int k = 0; k < DDEPTH; k++) { w[k] = expf(ds[k] - m); ssum += w[k]; }
    float cd = 0.f;
    for (int k = DDEPTH - 1; k >= d; --k) cd += w[k] / ssum;
    __syncthreads();

    const float* fbase = fs + (size_t)di * GRIDN * HIDN;
    float* Tb = g_T + (size_t)di * NT * TROW;
    float a1 = 0.f, a2 = 0.f;
    ((float2*)Tb)[h] = make_float2(0.f, 0.f);
    for (int t0 = 0; t0 < GRIDN; t0 += 4) {
        int p0 = spm[t0 + 0], p1 = spm[t0 + 1], p2 = spm[t0 + 2], p3 = spm[t0 + 3];
        float f0 = fbase[p0 * HIDN + h];
        float f1 = fbase[p1 * HIDN + h];
        float f2 = fbase[p2 * HIDN + h];
        float f3 = fbase[p3 * HIDN + h];
        a1 += f0; a2 = fmaf(ssg[t0 + 0], f0, a2);
        ((float2*)(Tb + (size_t)(t0 + 1) * TROW))[h] = make_float2(cd * a1, cd * a2);
        a1 += f1; a2 = fmaf(ssg[t0 + 1], f1, a2);
        ((float2*)(Tb + (size_t)(t0 + 2) * TROW))[h] = make_float2(cd * a1, cd * a2);
        a1 += f2; a2 = fmaf(ssg[t0 + 2], f2, a2);
        ((float2*)(Tb + (size_t)(t0 + 3) * TROW))[h] = make_float2(cd * a1, cd * a2);
        a1 += f3; a2 = fmaf(ssg[t0 + 3], f3, a2);
        ((float2*)(Tb + (size_t)(t0 + 4) * TROW))[h] = make_float2(cd * a1, cd * a2);
    }
}

// ---------------- 5. t[d,i,b] = #{ g < z } ----------------
__global__ void k_tmap() {
    int di = blockIdx.x;
    __shared__ float sg[GRIDN];
    if (threadIdx.x < GRIDN) sg[threadIdx.x] = g_sg[di * GRIDN + threadIdx.x];
    __syncthreads();
    int i = di & (IND - 1);
    for (int b = threadIdx.x; b < BATCHN; b += blockDim.x) {
        float z = g_Zt[i * BATCHN + b];
        int t = 0;
        #pragma unroll
        for (int s = 64; s > 0; s >>= 1) {
            int nt = t + s;
            if (nt <= GRIDN && sg[nt - 1] < z) t = nt;
        }
        g_tmap[(size_t)di * BATCHN + b] = (unsigned char)t;
    }
}

// ---------------- 6. main kernel: smem-staged rows, register accumulators ----------------
// grid = 128: bc = x&3 (512 b), hc = (x>>2)&3 (64 h), ic = x>>4 (16 i)
// 512 threads: hx = tid&31 (h-pair hc*32+hx), bg = tid>>5 (32 b's each)
// Per (d,i) step: stage all 129 rows' 64-h slice (66KB) via cp.async (double buffered),
// then each thread gathers rowbuf[t_b][hx] for its 32 batches. Table has c_d pre-folded:
// contribution = z*V1 - V2.
__global__ void __launch_bounds__(MAIN_TPB, 1) k_main() {
    extern __shared__ float4 smem4[];
    float4* rowbuf = smem4;                         // [2][STAGE_N]
    float*  z_s    = (float*)(smem4 + 2 * STAGE_N); // [IPC][BCB]

    int bc = blockIdx.x & 3;
    int hc = (blockIdx.x >> 2) & 3;
    int ic = blockIdx.x >> 4;
    int tid = threadIdx.x;
    int hx = tid & 31;
    int bg = tid >> 5;          // 0..15
    int b0 = bc * BCB;
    int i0 = ic * IPC;

    // stage z slice: z_s[il][bl] = g_Zt[i0+il][b0+bl]  (coalesced)
    for (int idx = tid; idx < IPC * BCB; idx += MAIN_TPB) {
        int il = idx >> 9, bl = idx & (BCB - 1);
        z_s[idx] = g_Zt[(i0 + il) * BATCHN + b0 + bl];
    }

    float2 acc[32];
    #pragma unroll
    for (int j = 0; j < 32; j++) acc[j] = make_float2(0.f, 0.f);

    // stage step s = il*7 + d
    auto stage = [&](int s, int buf) {
        int il = s / DDEPTH;
        int d  = s - il * DDEPTH;
        const float* src = g_T + (size_t)(d * IND + i0 + il) * (NT * TROW) + hc * 128;
        float4* dst = rowbuf + buf * STAGE_N;
        for (int idx = tid; idx < STAGE_N; idx += MAIN_TPB) {
            int row = idx >> 5, col = idx & 31;
            cp16(&dst[idx], src + (size_t)row * TROW + col * 4);
        }
        CP_COMMIT();
    };

    stage(0, 0);
    __syncthreads();   // z_s ready

    const int NS = IPC * DDEPTH;   // 112
    for (int s = 0; s < NS; s++) {
        if (s + 1 < NS) { stage(s + 1, (s + 1) & 1); CP_WAIT1(); }
        else           { CP_WAIT0(); }
        __syncthreads();           // buffer s complete across all threads

        int il = s / DDEPTH;
        int d  = s - il * DDEPTH;
        const float4* rb = rowbuf + (s & 1) * STAGE_N;
        const unsigned int* tbw = (const unsigned int*)
            (g_tmap + (size_t)(d * IND + i0 + il) * BATCHN + b0 + bg * 32);
        const float* zb = z_s + il * BCB + bg * 32;

        #pragma unroll
        for (int q = 0; q < 8; q++) {
            unsigned int tw = tbw[q];
            float4 z4 = *(const float4*)(zb + q * 4);
            float4 v0 = rb[(tw & 255u) * 32 + hx];
            float4 v1 = rb[((tw >> 8) & 255u) * 32 + hx];
            float4 v2 = rb[((tw >> 16) & 255u) * 32 + hx];
            float4 v3 = rb[(tw >> 24) * 32 + hx];
            acc[q*4+0].x = fmaf(z4.x, v0.x, acc[q*4+0].x - v0.y);
            acc[q*4+0].y = fmaf(z4.x, v0.z, acc[q*4+0].y - v0.w);
            acc[q*4+1].x = fmaf(z4.y, v1.x, acc[q*4+1].x - v1.y);
            acc[q*4+1].y = fmaf(z4.y, v1.z, acc[q*4+1].y - v1.w);
            acc[q*4+2].x = fmaf(z4.z, v2.x, acc[q*4+2].x - v2.y);
            acc[q*4+2].y = fmaf(z4.z, v2.z, acc[q*4+2].y - v2.w);
            acc[q*4+3].x = fmaf(z4.w, v3.x, acc[q*4+3].x - v3.y);
            acc[q*4+3].y = fmaf(z4.w, v3.z, acc[q*4+3].y - v3.w);
        }
        __syncthreads();           // done reading buffer s; next stage may overwrite it
    }

    // write partials: h0 = 2*(hc*32+hx)
    int h0 = (hc * 32 + hx) * 2;
    float* outp = g_Hp + (size_t)ic * BATCHN * HIDN;
    #pragma unroll
    for (int j = 0; j < 32; j++) {
        int b = b0 + bg * 32 + j;
        *(float2*)&outp[(size_t)b * HIDN + h0] = acc[j];
    }
}

// ---------------- 7. MLP head ----------------
__global__ void k_zstat() {
    int t = threadIdx.x;
    g_sum[t] = 0.0; g_sumsq[t] = 0.0;
}

__device__ __forceinline__ float gelu_exact(float y) {
    return 0.5f * y * (1.0f + erff(y * 0.70710678118654752440f));
}

// act==0: src = g_Hp, sum NIC partials. act==1: BN(prev params)+GELU on src.
__global__ void __launch_bounds__(256) k_gemm(const float* __restrict__ W,
                                              const float* __restrict__ bias,
                                              const float* __restrict__ src,
                                              float* __restrict__ dst,
                                              int act) {
    __shared__ float Hs[16 * HIDN];
    int b0 = blockIdx.x * 16;
    int tid = threadIdx.x;
    for (int idx = tid; idx < 16 * HIDN; idx += 256) {
        size_t off = (size_t)b0 * HIDN + idx;
        float v;
        if (act) {
            v = src[off];
            float2 p = g_bnp[idx & (HIDN - 1)];
            v = gelu_exact(fmaf(v, p.x, p.y));
        } else {
            v = 0.f;
            #pragma unroll
            for (int p = 0; p < NIC; p++)
                v += src[(size_t)p * BATCHN * HIDN + off];
        }
        Hs[idx] = v;
    }
    __syncthreads();

    float acc[16];
    #pragma unroll
    for (int b = 0; b < 16; b++) acc[b] = 0.f;
    int hxc = tid;
    for (int k4 = 0; k4 < HIDN / 4; k4++) {
        float w0 = W[(4 * k4 + 0) * HIDN + hxc];
        float w1 = W[(4 * k4 + 1) * HIDN + hxc];
        float w2 = W[(4 * k4 + 2) * HIDN + hxc];
        float w3 = W[(4 * k4 + 3) * HIDN + hxc];
        #pragma unroll
        for (int b = 0; b < 16; b++) {
            float4 hv = *(const float4*)&Hs[b * HIDN + 4 * k4];
            acc[b] = fmaf(hv.x, w0, fmaf(hv.y, w1, fmaf(hv.z, w2, fmaf(hv.w, w3, acc[b]))));
        }
    }
    float bsv = bias[hxc];
    double s1 = 0.0, s2 = 0.0;
    #pragma unroll
    for (int b = 0; b < 16; b++) {
        float y = acc[b] + bsv;
        dst[(size_t)(b0 + b) * HIDN + hxc] = y;
        s1 += (double)y;
        s2 += (double)y * (double)y;
    }
    atomicAdd(&g_sum[hxc], s1);
    atomicAdd(&g_sumsq[hxc], s2);
}

__global__ void k_bnfin(const float* __restrict__ gamma, const float* __restrict__ beta) {
    int h = threadIdx.x;
    double mean = g_sum[h] / (double)BATCHN;
    double var  = g_sumsq[h] / (double)BATCHN - mean * mean;
    float scale = gamma[h] * rsqrtf((float)var + 1e-5f);
    float shift = beta[h] - (float)mean * scale;
    g_bnp[h] = make_float2(scale, shift);
    g_sum[h] = 0.0; g_sumsq[h] = 0.0;
}

__global__ void k_final(const float* __restrict__ Wout, const float* __restrict__ bout,
                        float* __restrict__ out) {
    int b = blockIdx.x * 8 + (threadIdx.x >> 5);
    int lane = threadIdx.x & 31;
    const float* hr = g_Hb + (size_t)b * HIDN;
    float s = 0.f;
    #pragma unroll
    for (int k = lane; k < HIDN; k += 32) {
        float2 p = g_bnp[k];
        float y = gelu_exact(fmaf(hr[k], p.x, p.y));
        s = fmaf(y, Wout[k], s);
    }
    #pragma unroll
    for (int o = 16; o > 0; o >>= 1) s += __shfl_down_sync(0xffffffffu, s, o);
    if (lane == 0) out[b] = s + bout[0];
}

// ---------------- launch ----------------
extern "C" void kernel_launch(void* const* d_in, const int* in_sizes, int n_in,
                              void* d_out, int out_size) {
    const float* x     = (const float*)d_in[0];
    const float* grids = (const float*)d_in[1];
    const float* fs    = (const float*)d_in[2];
    const float* ds    = (const float*)d_in[3];
    const float* mlpW  = (const float*)d_in[4];
    const float* mlpb  = (const float*)d_in[5];
    const float* gamma = (const float*)d_in[6];
    const float* beta  = (const float*)d_in[7];
    const float* Wout  = (const float*)d_in[8];
    const float* bout  = (const float*)d_in[9];
    float* out = (float*)d_out;

    float* Ha; float* Hb; float* Hp;
    cudaGetSymbolAddress((void**)&Ha, g_Ha);
    cudaGetSymbolAddress((void**)&Hb, g_Hb);
    cudaGetSymbolAddress((void**)&Hp, g_Hp);

    cudaFuncSetAttribute(k_main, cudaFuncAttributeMaxDynamicSharedMemorySize, SMEM_MAIN);

    k_minmax<<<IND, 256>>>(x);
    k_z<<<(BATCHN * IND + 255) / 256, 256>>>(x);
    k_sort<<<DDEPTH * IND, GRIDN>>>(grids);
    k_table<<<DDEPTH * IND, HIDN>>>(fs, ds);
    k_tmap<<<DDEPTH * IND, 256>>>();
    k_main<<<128, MAIN_TPB, SMEM_MAIN>>>();

    k_zstat<<<1, HIDN>>>();
    k_gemm<<<BATCHN / 16, 256>>>(mlpW + 0 * HIDN * HIDN, mlpb + 0 * HIDN, Hp, Hb, 0);
    k_bnfin<<<1, HIDN>>>(gamma + 0 * HIDN, beta + 0 * HIDN);
    k_gemm<<<BATCHN / 16, 256>>>(mlpW + 1 * HIDN * HIDN, mlpb + 1 * HIDN, Hb, Ha, 1);
    k_bnfin<<<1, HIDN>>>(gamma + 1 * HIDN, beta + 1 * HIDN);
    k_gemm<<<BATCHN / 16, 256>>>(mlpW + 2 * HIDN * HIDN, mlpb + 2 * HIDN, Ha, Hb, 1);
    k_bnfin<<<1, HIDN>>>(gamma + 2 * HIDN, beta + 2 * HIDN);
    k_final<<<BATCHN / 8, 256>>>(Wout, bout, out);
}

// round 6
// speedup vs baseline: 1.5999x; 1.5999x over previous
#include <cuda_runtime.h>
#include <math.h>
#include <float.h>

#define DDEPTH 7
#define IND   128
#define GRIDN 128
#define HIDN  256
#define BATCHN 2048
#define NT    129          // t in 0..128
#define TROW  512          // floats per (d,i) per t across all h: (P1,P2) per h

// k_main tiling
#define MAIN_TPB 512
#define BCB   512          // batches per CTA
#define IPC   16           // i's per CTA
#define NIC   8            // i-chunk count (128/IPC)
#define HCN   4            // h chunks (64 h each)
#define CHUNKF 128         // floats per t-row within one h-chunk (64 h * 2)
#define ROWF4 32           // float4 per chunk row
#define STAGE_N (NT * ROWF4)                 // 4128 float4 per buffer
#define STAGE_BYTES (NT * CHUNKF * 4)        // 66048 bytes
#define SMEM_MAIN (2 * STAGE_N * 16 + IPC * BCB * 4 + 32)

// ---------------- scratch (static device memory; no allocation) ----------------
__device__ float g_xmin[IND];
__device__ float g_xmax[IND];
__device__ float g_Zt[IND * BATCHN];             // z transposed: [i][b]
__device__ float g_sg[DDEPTH * IND * GRIDN];     // sorted grids
__device__ int   g_perm[DDEPTH * IND * GRIDN];   // permutation
// layout: [d][i][hc][t][128 floats]  (c_d folded in)
__device__ float g_T[(size_t)DDEPTH * IND * NT * TROW];
__device__ unsigned char g_tmap[(size_t)DDEPTH * IND * BATCHN];
__device__ float g_Hp[(size_t)NIC * BATCHN * HIDN];       // i-split partials
__device__ float g_Ha[BATCHN * HIDN];
__device__ float g_Hb[BATCHN * HIDN];
__device__ double g_sum[HIDN];
__device__ double g_sumsq[HIDN];
__device__ float2 g_bnp[HIDN];

// ---------------- mbarrier + bulk-copy helpers ----------------
__device__ __forceinline__ unsigned int smem_u32(const void* p) {
    return (unsigned int)__cvta_generic_to_shared(p);
}
__device__ __forceinline__ void mbar_init(unsigned int a, unsigned int cnt) {
    asm volatile("mbarrier.init.shared.b64 [%0], %1;" :: "r"(a), "r"(cnt) : "memory");
}
__device__ __forceinline__ void mbar_expect(unsigned int a, unsigned int tx) {
    asm volatile("mbarrier.arrive.expect_tx.shared.b64 _, [%0], %1;" :: "r"(a), "r"(tx) : "memory");
}
__device__ __forceinline__ void bulk_g2s(unsigned int dst, const void* src,
                                         unsigned int bytes, unsigned int mbar) {
    asm volatile("cp.async.bulk.shared::cta.global.mbarrier::complete_tx::bytes [%0], [%1], %2, [%3];"
                 :: "r"(dst), "l"(src), "r"(bytes), "r"(mbar) : "memory");
}
__device__ __forceinline__ void mbar_wait(unsigned int a, unsigned int parity) {
    asm volatile(
        "{\n\t"
        ".reg .pred P;\n\t"
        "W_%=:\n\t"
        "mbarrier.try_wait.parity.acquire.cta.shared::cta.b64 P, [%0], %1;\n\t"
        "@P bra D_%=;\n\t"
        "bra W_%=;\n\t"
        "D_%=:\n\t"
        "}"
        :: "r"(a), "r"(parity) : "memory");
}

// ---------------- 1. per-feature min/max over batch ----------------
__global__ void k_minmax(const float* __restrict__ x) {
    int i = blockIdx.x;
    float mn = FLT_MAX, mx = -FLT_MAX;
    for (int b = threadIdx.x; b < BATCHN; b += blockDim.x) {
        float v = x[b * IND + i];
        mn = fminf(mn, v);
        mx = fmaxf(mx, v);
    }
    __shared__ float smn[256], smx[256];
    smn[threadIdx.x] = mn; smx[threadIdx.x] = mx;
    __syncthreads();
    for (int s = 128; s > 0; s >>= 1) {
        if (threadIdx.x < s) {
            smn[threadIdx.x] = fminf(smn[threadIdx.x], smn[threadIdx.x + s]);
            smx[threadIdx.x] = fmaxf(smx[threadIdx.x], smx[threadIdx.x + s]);
        }
        __syncthreads();
    }
    if (threadIdx.x == 0) { g_xmin[i] = smn[0]; g_xmax[i] = smx[0]; }
}

// ---------------- 2. z transposed: g_Zt[i][b] ----------------
__global__ void k_z(const float* __restrict__ x) {
    int idx = blockIdx.x * blockDim.x + threadIdx.x;
    if (idx < BATCHN * IND) {
        int i = idx & (IND - 1);
        int b = idx >> 7;
        g_Zt[i * BATCHN + b] = (x[idx] - g_xmin[i]) / (g_xmax[i] - g_xmin[i] + 1e-6f);
    }
}

// ---------------- 3. sort grids per (d,i) via rank ----------------
__global__ void k_sort(const float* __restrict__ grids) {
    int di = blockIdx.x;
    int t  = threadIdx.x;
    __shared__ float sg[GRIDN];
    float g = grids[di * GRIDN + t];
    sg[t] = g;
    __syncthreads();
    int r = 0;
    #pragma unroll 8
    for (int j = 0; j < GRIDN; j++) {
        float gj = sg[j];
        r += (gj < g) || (gj == g && j < t);
    }
    g_sg[di * GRIDN + r]   = g;
    g_perm[di * GRIDN + r] = t;
}

// ---------------- 4. prefix tables with c_d folded; chunked layout ----------------
__global__ void __launch_bounds__(256) k_table(const float* __restrict__ fs,
                                               const float* __restrict__ ds) {
    __shared__ float ssg[GRIDN];
    __shared__ int   spm[GRIDN];
    int di = blockIdx.x;
    int d  = di >> 7;
    int h  = threadIdx.x;
    if (h < GRIDN) {
        ssg[h] = g_sg[di * GRIDN + h];
        spm[h] = g_perm[di * GRIDN + h];
    }
    float w[DDEPTH], m = -FLT_MAX;
    for (int k = 0; k < DDEPTH; k++) m = fmaxf(m, ds[k]);
    float ssum = 0.f;
    for (int k = 0; k < DDEPTH; k++) { w[k] = expf(ds[k] - m); ssum += w[k]; }
    float cd = 0.f;
    for (int k = DDEPTH - 1; k >= d; --k) cd += w[k] / ssum;
    __syncthreads();

    const float* fbase = fs + (size_t)di * GRIDN * HIDN;
    // store base for this h: chunk hc = h>>6, offset (h&63)*2 inside 128-float row
    float* base = g_T + (size_t)di * NT * TROW + (h >> 6) * (NT * CHUNKF) + (h & 63) * 2;
    float a1 = 0.f, a2 = 0.f;
    *(float2*)base = make_float2(0.f, 0.f);        // t = 0 row
    for (int t0 = 0; t0 < GRIDN; t0 += 4) {
        int p0 = spm[t0 + 0], p1 = spm[t0 + 1], p2 = spm[t0 + 2], p3 = spm[t0 + 3];
        float f0 = fbase[p0 * HIDN + h];
        float f1 = fbase[p1 * HIDN + h];
        float f2 = fbase[p2 * HIDN + h];
        float f3 = fbase[p3 * HIDN + h];
        a1 += f0; a2 = fmaf(ssg[t0 + 0], f0, a2);
        *(float2*)(base + (size_t)(t0 + 1) * CHUNKF) = make_float2(cd * a1, cd * a2);
        a1 += f1; a2 = fmaf(ssg[t0 + 1], f1, a2);
        *(float2*)(base + (size_t)(t0 + 2) * CHUNKF) = make_float2(cd * a1, cd * a2);
        a1 += f2; a2 = fmaf(ssg[t0 + 2], f2, a2);
        *(float2*)(base + (size_t)(t0 + 3) * CHUNKF) = make_float2(cd * a1, cd * a2);
        a1 += f3; a2 = fmaf(ssg[t0 + 3], f3, a2);
        *(float2*)(base + (size_t)(t0 + 4) * CHUNKF) = make_float2(cd * a1, cd * a2);
    }
}

// ---------------- 5. t[d,i,b] = #{ g < z } ----------------
__global__ void k_tmap() {
    int di = blockIdx.x;
    __shared__ float sg[GRIDN];
    if (threadIdx.x < GRIDN) sg[threadIdx.x] = g_sg[di * GRIDN + threadIdx.x];
    __syncthreads();
    int i = di & (IND - 1);
    for (int b = threadIdx.x; b < BATCHN; b += blockDim.x) {
        float z = g_Zt[i * BATCHN + b];
        int t = 0;
        #pragma unroll
        for (int s = 64; s > 0; s >>= 1) {
            int nt = t + s;
            if (nt <= GRIDN && sg[nt - 1] < z) t = nt;
        }
        g_tmap[(size_t)di * BATCHN + b] = (unsigned char)t;
    }
}

// ---------------- 6. main kernel: bulk-staged rows, register accumulators ----------------
// grid = 128: bc = x&3 (512 b), hc = (x>>2)&3 (64 h), ic = x>>4 (16 i).
// 512 threads: hx = tid&31 (h-pair index in chunk), bg = tid>>5 (32 b's each).
// Per (d,i) step: ONE cp.async.bulk stages the contiguous 66KB (d,i,hc) slice
// (double-buffered, mbarrier expect_tx); all threads gather rowbuf[t*32+hx].
__global__ void __launch_bounds__(MAIN_TPB, 1) k_main() {
    extern __shared__ float4 smem4[];
    float4* rowbuf = smem4;                               // [2][STAGE_N]
    float*  z_s    = (float*)(smem4 + 2 * STAGE_N);       // [IPC][BCB]
    unsigned long long* mbar = (unsigned long long*)(z_s + IPC * BCB);  // [2]

    int bc = blockIdx.x & 3;
    int hc = (blockIdx.x >> 2) & 3;
    int ic = blockIdx.x >> 4;
    int tid = threadIdx.x;
    int hx = tid & 31;
    int bg = tid >> 5;
    int b0 = bc * BCB;
    int i0 = ic * IPC;

    unsigned int mb0 = smem_u32(&mbar[0]);
    unsigned int mb1 = smem_u32(&mbar[1]);
    unsigned int rb0 = smem_u32(&rowbuf[0]);
    unsigned int rb1 = smem_u32(&rowbuf[STAGE_N]);

    if (tid == 0) { mbar_init(mb0, 1); mbar_init(mb1, 1); }

    // stage z slice (coalesced)
    for (int idx = tid; idx < IPC * BCB; idx += MAIN_TPB) {
        int il = idx >> 9, bl = idx & (BCB - 1);
        z_s[idx] = g_Zt[(i0 + il) * BATCHN + b0 + bl];
    }
    __syncthreads();   // mbar init + z_s visible

    const int NS = IPC * DDEPTH;   // 112
    // src for step s = il*7+d: contiguous slice [d][i0+il][hc]
    auto src_of = [&](int s) -> const float* {
        int il = s / DDEPTH;
        int d  = s - il * DDEPTH;
        return g_T + (size_t)(d * IND + i0 + il) * (NT * TROW) + (size_t)hc * (NT * CHUNKF);
    };

    if (tid == 0) { mbar_expect(mb0, STAGE_BYTES); bulk_g2s(rb0, src_of(0), STAGE_BYTES, mb0); }

    float2 acc[32];
    #pragma unroll
    for (int j = 0; j < 32; j++) acc[j] = make_float2(0.f, 0.f);

    unsigned int ph0 = 0, ph1 = 0;

    for (int s = 0; s < NS; s++) {
        // issue next stage into the other buffer (safe: its readers finished at
        // the __syncthreads ending step s-1)
        if (s + 1 < NS && tid == 0) {
            if ((s + 1) & 1) { mbar_expect(mb1, STAGE_BYTES); bulk_g2s(rb1, src_of(s + 1), STAGE_BYTES, mb1); }
            else             { mbar_expect(mb0, STAGE_BYTES); bulk_g2s(rb0, src_of(s + 1), STAGE_BYTES, mb0); }
        }
        // wait for buffer s
        if (s & 1) { mbar_wait(mb1, ph1); ph1 ^= 1; }
        else       { mbar_wait(mb0, ph0); ph0 ^= 1; }

        int il = s / DDEPTH;
        int d  = s - il * DDEPTH;
        const float4* rb = rowbuf + (s & 1) * STAGE_N;
        const unsigned int* tbw = (const unsigned int*)
            (g_tmap + (size_t)(d * IND + i0 + il) * BATCHN + b0 + bg * 32);
        const float* zb = z_s + il * BCB + bg * 32;

        #pragma unroll
        for (int q = 0; q < 8; q++) {
            unsigned int tw = tbw[q];
            float4 z4 = *(const float4*)(zb + q * 4);
            float4 v0 = rb[(tw & 255u) * 32 + hx];
            float4 v1 = rb[((tw >> 8) & 255u) * 32 + hx];
            float4 v2 = rb[((tw >> 16) & 255u) * 32 + hx];
            float4 v3 = rb[(tw >> 24) * 32 + hx];
            acc[q*4+0].x = fmaf(z4.x, v0.x, acc[q*4+0].x - v0.y);
            acc[q*4+0].y = fmaf(z4.x, v0.z, acc[q*4+0].y - v0.w);
            acc[q*4+1].x = fmaf(z4.y, v1.x, acc[q*4+1].x - v1.y);
            acc[q*4+1].y = fmaf(z4.y, v1.z, acc[q*4+1].y - v1.w);
            acc[q*4+2].x = fmaf(z4.z, v2.x, acc[q*4+2].x - v2.y);
            acc[q*4+2].y = fmaf(z4.z, v2.z, acc[q*4+2].y - v2.w);
            acc[q*4+3].x = fmaf(z4.w, v3.x, acc[q*4+3].x - v3.y);
            acc[q*4+3].y = fmaf(z4.w, v3.z, acc[q*4+3].y - v3.w);
        }
        __syncthreads();   // all threads done reading buffer s before it is re-staged
    }

    int h0 = (hc * 32 + hx) * 2;
    float* outp = g_Hp + (size_t)ic * BATCHN * HIDN;
    #pragma unroll
    for (int j = 0; j < 32; j++) {
        int b = b0 + bg * 32 + j;
        *(float2*)&outp[(size_t)b * HIDN + h0] = acc[j];
    }
}

// ---------------- 7. MLP head ----------------
__global__ void k_zstat() {
    int t = threadIdx.x;
    g_sum[t] = 0.0; g_sumsq[t] = 0.0;
}

__device__ __forceinline__ float gelu_exact(float y) {
    return 0.5f * y * (1.0f + erff(y * 0.70710678118654752440f));
}

// act==0: src = g_Hp, sum NIC partials. act==1: BN(prev params)+GELU on src.
__global__ void __launch_bounds__(256) k_gemm(const float* __restrict__ W,
                                              const float* __restrict__ bias,
                                              const float* __restrict__ src,
                                              float* __restrict__ dst,
                                              int act) {
    __shared__ float Hs[16 * HIDN];
    int b0 = blockIdx.x * 16;
    int tid = threadIdx.x;
    for (int idx = tid; idx < 16 * HIDN; idx += 256) {
        size_t off = (size_t)b0 * HIDN + idx;
        float v;
        if (act) {
            v = src[off];
            float2 p = g_bnp[idx & (HIDN - 1)];
            v = gelu_exact(fmaf(v, p.x, p.y));
        } else {
            v = 0.f;
            #pragma unroll
            for (int p = 0; p < NIC; p++)
                v += src[(size_t)p * BATCHN * HIDN + off];
        }
        Hs[idx] = v;
    }
    __syncthreads();

    float acc[16];
    #pragma unroll
    for (int b = 0; b < 16; b++) acc[b] = 0.f;
    int hxc = tid;
    for (int k4 = 0; k4 < HIDN / 4; k4++) {
        float w0 = W[(4 * k4 + 0) * HIDN + hxc];
        float w1 = W[(4 * k4 + 1) * HIDN + hxc];
        float w2 = W[(4 * k4 + 2) * HIDN + hxc];
        float w3 = W[(4 * k4 + 3) * HIDN + hxc];
        #pragma unroll
        for (int b = 0; b < 16; b++) {
            float4 hv = *(const float4*)&Hs[b * HIDN + 4 * k4];
            acc[b] = fmaf(hv.x, w0, fmaf(hv.y, w1, fmaf(hv.z, w2, fmaf(hv.w, w3, acc[b]))));
        }
    }
    float bsv = bias[hxc];
    double s1 = 0.0, s2 = 0.0;
    #pragma unroll
    for (int b = 0; b < 16; b++) {
        float y = acc[b] + bsv;
        dst[(size_t)(b0 + b) * HIDN + hxc] = y;
        s1 += (double)y;
        s2 += (double)y * (double)y;
    }
    atomicAdd(&g_sum[hxc], s1);
    atomicAdd(&g_sumsq[hxc], s2);
}

__global__ void k_bnfin(const float* __restrict__ gamma, const float* __restrict__ beta) {
    int h = threadIdx.x;
    double mean = g_sum[h] / (double)BATCHN;
    double var  = g_sumsq[h] / (double)BATCHN - mean * mean;
    float scale = gamma[h] * rsqrtf((float)var + 1e-5f);
    float shift = beta[h] - (float)mean * scale;
    g_bnp[h] = make_float2(scale, shift);
    g_sum[h] = 0.0; g_sumsq[h] = 0.0;
}

__global__ void k_final(const float* __restrict__ Wout, const float* __restrict__ bout,
                        float* __restrict__ out) {
    int b = blockIdx.x * 8 + (threadIdx.x >> 5);
    int lane = threadIdx.x & 31;
    const float* hr = g_Hb + (size_t)b * HIDN;
    float s = 0.f;
    #pragma unroll
    for (int k = lane; k < HIDN; k += 32) {
        float2 p = g_bnp[k];
        float y = gelu_exact(fmaf(hr[k], p.x, p.y));
        s = fmaf(y, Wout[k], s);
    }
    #pragma unroll
    for (int o = 16; o > 0; o >>= 1) s += __shfl_down_sync(0xffffffffu, s, o);
    if (lane == 0) out[b] = s + bout[0];
}

// ---------------- launch ----------------
extern "C" void kernel_launch(void* const* d_in, const int* in_sizes, int n_in,
                              void* d_out, int out_size) {
    const float* x     = (const float*)d_in[0];
    const float* grids = (const float*)d_in[1];
    const float* fs    = (const float*)d_in[2];
    const float* ds    = (const float*)d_in[3];
    const float* mlpW  = (const float*)d_in[4];
    const float* mlpb  = (const float*)d_in[5];
    const float* gamma = (const float*)d_in[6];
    const float* beta  = (const float*)d_in[7];
    const float* Wout  = (const float*)d_in[8];
    const float* bout  = (const float*)d_in[9];
    float* out = (float*)d_out;

    float* Ha; float* Hb; float* Hp;
    cudaGetSymbolAddress((void**)&Ha, g_Ha);
    cudaGetSymbolAddress((void**)&Hb, g_Hb);
    cudaGetSymbolAddress((void**)&Hp, g_Hp);

    cudaFuncSetAttribute(k_main, cudaFuncAttributeMaxDynamicSharedMemorySize, SMEM_MAIN);

    k_minmax<<<IND, 256>>>(x);
    k_z<<<(BATCHN * IND + 255) / 256, 256>>>(x);
    k_sort<<<DDEPTH * IND, GRIDN>>>(grids);
    k_table<<<DDEPTH * IND, HIDN>>>(fs, ds);
    k_tmap<<<DDEPTH * IND, 256>>>();
    k_main<<<128, MAIN_TPB, SMEM_MAIN>>>();

    k_zstat<<<1, HIDN>>>();
    k_gemm<<<BATCHN / 16, 256>>>(mlpW + 0 * HIDN * HIDN, mlpb + 0 * HIDN, Hp, Hb, 0);
    k_bnfin<<<1, HIDN>>>(gamma + 0 * HIDN, beta + 0 * HIDN);
    k_gemm<<<BATCHN / 16, 256>>>(mlpW + 1 * HIDN * HIDN, mlpb + 1 * HIDN, Hb, Ha, 1);
    k_bnfin<<<1, HIDN>>>(gamma + 1 * HIDN, beta + 1 * HIDN);
    k_gemm<<<BATCHN / 16, 256>>>(mlpW + 2 * HIDN * HIDN, mlpb + 2 * HIDN, Ha, Hb, 1);
    k_bnfin<<<1, HIDN>>>(gamma + 2 * HIDN, beta + 2 * HIDN);
    k_final<<<BATCHN / 8, 256>>>(Wout, bout, out);
}